// round 11
// baseline (speedup 1.0000x reference)
#include <cuda_runtime.h>
#include <stdint.h>

// RoPE: x (B,H,S,128) fp32, token_positions (S,) int32,
// cos_table/sin_table (8192, 64) fp32.
//
// Final config (best kernel time across R1-R9 sweep = R7 structure):
//  - grid-stride, UN=4 (per-thread MLP sweet spot)
//  - plain __launch_bounds__(256): 32 regs, ~80% occupancy
//  - default-cached loads (x populates L2), __stwt stores (write-through,
//    no L2 churn)
//  - pointer-increment addressing (IADD per step)
// The op is at the mixed R/W HBM ceiling (~75% of 8TB/s).

#define THREADS 256
#define UN 4

template<bool POW2>
__global__ void __launch_bounds__(THREADS)
rope_bulk(const float4* __restrict__ x,
          const int*    __restrict__ tok_pos,
          const float2* __restrict__ cos_t,   // row stride 32 float2
          const float2* __restrict__ sin_t,
          float4*       __restrict__ out,
          int seq, int seq_mask)
{
    const int stride = gridDim.x * blockDim.x;
    const int base   = blockIdx.x * blockDim.x + threadIdx.x;
    const int q      = base & 31;              // float4 col (stride % 32 == 0)
    const int rstep  = stride >> 5;            // rows per k-step

    // Batch 1: 4 independent 16B loads (pointer-increment addressing)
    float4 v[UN];
    {
        const float4* xp = x + base;
#pragma unroll
        for (int k = 0; k < UN; k++) {
            v[k] = *xp;
            xp += stride;
        }
    }

    // Batch 2: token positions (tiny, cache-resident)
    int p[UN];
    {
        int row = base >> 5;
#pragma unroll
        for (int k = 0; k < UN; k++) {
            int pos = POW2 ? (row & seq_mask) : (row % seq);
            p[k] = __ldg(&tok_pos[pos]);
            row += rstep;
        }
    }

    // Batch 3: table gathers (L2-resident, warp-coalesced 256B)
    float2 c[UN], s[UN];
#pragma unroll
    for (int k = 0; k < UN; k++) {
        c[k] = __ldg(&cos_t[p[k] * 32 + q]);
        s[k] = __ldg(&sin_t[p[k] * 32 + q]);
    }

    // Compute + write-through stores
    {
        float4* op = out + base;
#pragma unroll
        for (int k = 0; k < UN; k++) {
            float4 o;
            o.x = fmaf(c[k].x, v[k].x, -s[k].x * v[k].y);
            o.y = fmaf(s[k].x, v[k].x,  c[k].x * v[k].y);
            o.z = fmaf(c[k].y, v[k].z, -s[k].y * v[k].w);
            o.w = fmaf(s[k].y, v[k].z,  c[k].y * v[k].w);
            __stwt(op, o);
            op += stride;
        }
    }
}

// Tail (only launches if n4 % (THREADS*UN) != 0; never for the bench shape).
template<bool POW2>
__global__ void __launch_bounds__(THREADS)
rope_tail(const float4* __restrict__ x,
          const int*    __restrict__ tok_pos,
          const float2* __restrict__ cos_t,
          const float2* __restrict__ sin_t,
          float4*       __restrict__ out,
          int start, int n4, int seq, int seq_mask)
{
    int i = start + blockIdx.x * blockDim.x + threadIdx.x;
    if (i >= n4) return;
    int row = i >> 5;
    int q   = i & 31;
    int pos = POW2 ? (row & seq_mask) : (row % seq);
    int p   = __ldg(&tok_pos[pos]);
    float2 c = __ldg(&cos_t[p * 32 + q]);
    float2 s = __ldg(&sin_t[p * 32 + q]);
    float4 v = x[i];
    float4 o;
    o.x = fmaf(c.x, v.x, -s.x * v.y);
    o.y = fmaf(s.x, v.x,  c.x * v.y);
    o.z = fmaf(c.y, v.z, -s.y * v.w);
    o.w = fmaf(s.y, v.z,  c.y * v.w);
    __stwt(&out[i], o);
}

extern "C" void kernel_launch(void* const* d_in, const int* in_sizes, int n_in,
                              void* d_out, int out_size)
{
    const float4* x     = (const float4*)d_in[0];
    const int*    tpos  = (const int*)   d_in[1];
    const float2* cos_t = (const float2*)d_in[2];
    const float2* sin_t = (const float2*)d_in[3];
    float4*       out   = (float4*)      d_out;

    int seq = in_sizes[1];
    int n4  = out_size / 4;

    const int chunk  = THREADS * UN;
    int  blocks = n4 / chunk;
    int  n_bulk = blocks * chunk;
    int  tail   = n4 - n_bulk;
    bool pow2   = (seq & (seq - 1)) == 0;

    if (blocks > 0) {
        if (pow2)
            rope_bulk<true ><<<blocks, THREADS>>>(x, tpos, cos_t, sin_t, out,
                                                  seq, seq - 1);
        else
            rope_bulk<false><<<blocks, THREADS>>>(x, tpos, cos_t, sin_t, out,
                                                  seq, 0);
    }
    if (tail > 0) {
        int tblocks = (tail + THREADS - 1) / THREADS;
        if (pow2)
            rope_tail<true ><<<tblocks, THREADS>>>(x, tpos, cos_t, sin_t, out,
                                                   n_bulk, n4, seq, seq - 1);
        else
            rope_tail<false><<<tblocks, THREADS>>>(x, tpos, cos_t, sin_t, out,
                                                   n_bulk, n4, seq, 0);
    }
}

// round 15
// speedup vs baseline: 1.0258x; 1.0258x over previous
#include <cuda_runtime.h>
#include <stdint.h>

// RoPE: x (B,H,S,128) fp32, token_positions (S,) int32,
// cos_table/sin_table (8192, 64) fp32.
//
// Bench-optimal cell of the R1-R11 matrix:
//  - block-contiguous CHUNK per CTA, compile-time immediate offsets
//    (best cross-replay L2 locality -> best bench wall time: R9/R4)
//  - plain __launch_bounds__(256): 32 regs, ~81% occupancy
//  - default-cached loads, __stwt write-through stores (no L2 churn)
//  - UN=4 (per-thread MLP sweet spot)

#define THREADS 256
#define UN 4
#define CHUNK (THREADS * UN)           // 1024 float4 per CTA

template<bool POW2>
__global__ void __launch_bounds__(THREADS)
rope_bulk(const float4* __restrict__ x,
          const int*    __restrict__ tok_pos,
          const float2* __restrict__ cos_t,   // row stride 32 float2
          const float2* __restrict__ sin_t,
          float4*       __restrict__ out,
          int seq, int seq_mask)
{
    const int t    = threadIdx.x;
    const int base = blockIdx.x * CHUNK + t;
    const float4* __restrict__ xp = x   + base;
    float4*       __restrict__ op = out + base;

    // Batch 1: 4 independent 16B loads at immediate offsets
    float4 v[UN];
#pragma unroll
    for (int k = 0; k < UN; k++)
        v[k] = xp[k * THREADS];

    // Batch 2: token positions (tiny, cache-resident)
    const int q    = t & 31;            // float4 col within 128-elem row
    const int row0 = base >> 5;
    int p[UN];
#pragma unroll
    for (int k = 0; k < UN; k++) {
        int row = row0 + k * (THREADS / 32);
        int pos = POW2 ? (row & seq_mask) : (row % seq);
        p[k] = __ldg(&tok_pos[pos]);
    }

    // Batch 3: table gathers (L2-resident, warp-coalesced 256B)
    float2 c[UN], s[UN];
#pragma unroll
    for (int k = 0; k < UN; k++) {
        c[k] = __ldg(&cos_t[p[k] * 32 + q]);
        s[k] = __ldg(&sin_t[p[k] * 32 + q]);
    }

    // Compute + write-through stores at immediate offsets
#pragma unroll
    for (int k = 0; k < UN; k++) {
        float4 o;
        o.x = fmaf(c[k].x, v[k].x, -s[k].x * v[k].y);
        o.y = fmaf(s[k].x, v[k].x,  c[k].x * v[k].y);
        o.z = fmaf(c[k].y, v[k].z, -s[k].y * v[k].w);
        o.w = fmaf(s[k].y, v[k].z,  c[k].y * v[k].w);
        __stwt(&op[k * THREADS], o);
    }
}

// Tail (only launches if n4 % CHUNK != 0; never for the bench shape).
template<bool POW2>
__global__ void __launch_bounds__(THREADS)
rope_tail(const float4* __restrict__ x,
          const int*    __restrict__ tok_pos,
          const float2* __restrict__ cos_t,
          const float2* __restrict__ sin_t,
          float4*       __restrict__ out,
          int start, int n4, int seq, int seq_mask)
{
    int i = start + blockIdx.x * blockDim.x + threadIdx.x;
    if (i >= n4) return;
    int row = i >> 5;
    int q   = i & 31;
    int pos = POW2 ? (row & seq_mask) : (row % seq);
    int p   = __ldg(&tok_pos[pos]);
    float2 c = __ldg(&cos_t[p * 32 + q]);
    float2 s = __ldg(&sin_t[p * 32 + q]);
    float4 v = x[i];
    float4 o;
    o.x = fmaf(c.x, v.x, -s.x * v.y);
    o.y = fmaf(s.x, v.x,  c.x * v.y);
    o.z = fmaf(c.y, v.z, -s.y * v.w);
    o.w = fmaf(s.y, v.z,  c.y * v.w);
    __stwt(&out[i], o);
}

extern "C" void kernel_launch(void* const* d_in, const int* in_sizes, int n_in,
                              void* d_out, int out_size)
{
    const float4* x     = (const float4*)d_in[0];
    const int*    tpos  = (const int*)   d_in[1];
    const float2* cos_t = (const float2*)d_in[2];
    const float2* sin_t = (const float2*)d_in[3];
    float4*       out   = (float4*)      d_out;

    int seq = in_sizes[1];
    int n4  = out_size / 4;

    int  blocks = n4 / CHUNK;
    int  n_bulk = blocks * CHUNK;
    int  tail   = n4 - n_bulk;
    bool pow2   = (seq & (seq - 1)) == 0;

    if (blocks > 0) {
        if (pow2)
            rope_bulk<true ><<<blocks, THREADS>>>(x, tpos, cos_t, sin_t, out,
                                                  seq, seq - 1);
        else
            rope_bulk<false><<<blocks, THREADS>>>(x, tpos, cos_t, sin_t, out,
                                                  seq, 0);
    }
    if (tail > 0) {
        int tblocks = (tail + THREADS - 1) / THREADS;
        if (pow2)
            rope_tail<true ><<<tblocks, THREADS>>>(x, tpos, cos_t, sin_t, out,
                                                   n_bulk, n4, seq, seq - 1);
        else
            rope_tail<false><<<tblocks, THREADS>>>(x, tpos, cos_t, sin_t, out,
                                                   n_bulk, n4, seq, 0);
    }
}

// round 17
// speedup vs baseline: 1.0446x; 1.0183x over previous
#include <cuda_runtime.h>
#include <stdint.h>

// RoPE: x (B,H,S,128) fp32, token_positions (S,) int32,
// cos_table/sin_table (8192, 64) fp32.
//
// 256-bit memory ops (sm_100+ ld/st.global.v8.f32):
//  - each item is a float8 = 4 rotation pairs; its table slice is exactly
//    one aligned float4 from cos and one from sin.
//  - block-contiguous CHUNK per CTA (bench-best cross-replay locality),
//    UN=2 float8/thread, write-through 256-bit stores.

#define THREADS 256
#define UN 2
#define CHUNK8 (THREADS * UN)          // 512 float8 per CTA (16KB)

struct f8 { float4 a, b; };

__device__ __forceinline__ f8 ldg256(const float* p)
{
    f8 r;
    asm volatile("ld.global.v8.f32 {%0,%1,%2,%3,%4,%5,%6,%7}, [%8];"
                 : "=f"(r.a.x), "=f"(r.a.y), "=f"(r.a.z), "=f"(r.a.w),
                   "=f"(r.b.x), "=f"(r.b.y), "=f"(r.b.z), "=f"(r.b.w)
                 : "l"(p));
    return r;
}

__device__ __forceinline__ void stg256_wt(float* p, const f8& v)
{
    asm volatile("st.global.wt.v8.f32 [%0], {%1,%2,%3,%4,%5,%6,%7,%8};"
                 :: "l"(p),
                    "f"(v.a.x), "f"(v.a.y), "f"(v.a.z), "f"(v.a.w),
                    "f"(v.b.x), "f"(v.b.y), "f"(v.b.z), "f"(v.b.w)
                 : "memory");
}

template<bool POW2>
__global__ void __launch_bounds__(THREADS)
rope_bulk(const float* __restrict__ x,
          const int*   __restrict__ tok_pos,
          const float4* __restrict__ cos_t,   // row = 16 float4
          const float4* __restrict__ sin_t,
          float*       __restrict__ out,
          int seq, int seq_mask)
{
    const int t     = threadIdx.x;
    const int base8 = blockIdx.x * CHUNK8 + t;      // float8 index
    const int q8    = t & 15;                       // float8 col in row (16/row)
    const int row0  = base8 >> 4;

    // Batch 1: 2 independent 32B loads at immediate offsets
    f8 v[UN];
#pragma unroll
    for (int k = 0; k < UN; k++)
        v[k] = ldg256(x + (size_t)(base8 + k * THREADS) * 8);

    // Batch 2: token positions (tiny, cache-resident)
    int p[UN];
#pragma unroll
    for (int k = 0; k < UN; k++) {
        int row = row0 + k * (THREADS / 16);
        int pos = POW2 ? (row & seq_mask) : (row % seq);
        p[k] = __ldg(&tok_pos[pos]);
    }

    // Batch 3: one float4 per table per item (L2-resident, coalesced)
    float4 c[UN], s[UN];
#pragma unroll
    for (int k = 0; k < UN; k++) {
        c[k] = __ldg(&cos_t[p[k] * 16 + q8]);
        s[k] = __ldg(&sin_t[p[k] * 16 + q8]);
    }

    // Compute + 256-bit write-through stores
#pragma unroll
    for (int k = 0; k < UN; k++) {
        f8 o;
        o.a.x = fmaf(c[k].x, v[k].a.x, -s[k].x * v[k].a.y);
        o.a.y = fmaf(s[k].x, v[k].a.x,  c[k].x * v[k].a.y);
        o.a.z = fmaf(c[k].y, v[k].a.z, -s[k].y * v[k].a.w);
        o.a.w = fmaf(s[k].y, v[k].a.z,  c[k].y * v[k].a.w);
        o.b.x = fmaf(c[k].z, v[k].b.x, -s[k].z * v[k].b.y);
        o.b.y = fmaf(s[k].z, v[k].b.x,  c[k].z * v[k].b.y);
        o.b.z = fmaf(c[k].w, v[k].b.z, -s[k].w * v[k].b.w);
        o.b.w = fmaf(s[k].w, v[k].b.z,  c[k].w * v[k].b.w);
        stg256_wt(out + (size_t)(base8 + k * THREADS) * 8, o);
    }
}

// Tail over float4 items (launches only if n4 % (CHUNK8*2) != 0; never here).
template<bool POW2>
__global__ void __launch_bounds__(THREADS)
rope_tail(const float4* __restrict__ x,
          const int*    __restrict__ tok_pos,
          const float2* __restrict__ cos_t,
          const float2* __restrict__ sin_t,
          float4*       __restrict__ out,
          int start, int n4, int seq, int seq_mask)
{
    int i = start + blockIdx.x * blockDim.x + threadIdx.x;
    if (i >= n4) return;
    int row = i >> 5;
    int q   = i & 31;
    int pos = POW2 ? (row & seq_mask) : (row % seq);
    int p   = __ldg(&tok_pos[pos]);
    float2 c = __ldg(&cos_t[p * 32 + q]);
    float2 s = __ldg(&sin_t[p * 32 + q]);
    float4 v = x[i];
    float4 o;
    o.x = fmaf(c.x, v.x, -s.x * v.y);
    o.y = fmaf(s.x, v.x,  c.x * v.y);
    o.z = fmaf(c.y, v.z, -s.y * v.w);
    o.w = fmaf(s.y, v.z,  c.y * v.w);
    __stwt(&out[i], o);
}

extern "C" void kernel_launch(void* const* d_in, const int* in_sizes, int n_in,
                              void* d_out, int out_size)
{
    const float*  x     = (const float*) d_in[0];
    const int*    tpos  = (const int*)   d_in[1];
    const float4* cos_t = (const float4*)d_in[2];
    const float4* sin_t = (const float4*)d_in[3];
    float*        out   = (float*)       d_out;

    int seq = in_sizes[1];
    int n4  = out_size / 4;            // float4 count
    int n8  = out_size / 8;            // float8 count

    int  blocks  = n8 / CHUNK8;        // bulk covers blocks*CHUNK8 float8s
    int  n_bulk4 = blocks * CHUNK8 * 2;
    int  tail4   = n4 - n_bulk4;
    bool pow2    = (seq & (seq - 1)) == 0;

    if (blocks > 0) {
        if (pow2)
            rope_bulk<true ><<<blocks, THREADS>>>(x, tpos, cos_t, sin_t, out,
                                                  seq, seq - 1);
        else
            rope_bulk<false><<<blocks, THREADS>>>(x, tpos, cos_t, sin_t, out,
                                                  seq, 0);
    }
    if (tail4 > 0) {
        int tblocks = (tail4 + THREADS - 1) / THREADS;
        if (pow2)
            rope_tail<true ><<<tblocks, THREADS>>>((const float4*)x, tpos,
                                                   (const float2*)cos_t,
                                                   (const float2*)sin_t,
                                                   (float4*)out,
                                                   n_bulk4, n4, seq, seq - 1);
        else
            rope_tail<false><<<tblocks, THREADS>>>((const float4*)x, tpos,
                                                   (const float2*)cos_t,
                                                   (const float2*)sin_t,
                                                   (float4*)out,
                                                   n_bulk4, n4, seq, 0);
    }
}